// round 7
// baseline (speedup 1.0000x reference)
#include <cuda_runtime.h>
#include <cuda_pipeline.h>
#include <math.h>

// Problem shape (fixed by reference setup_inputs)
#define BB 8
#define DD 64
#define HW (256 * 512)        // 131072
#define PIXELS (BB * HW)      // 1048576
#define TPB 256
#define NBLOCKS (PIXELS / 4 / TPB)   // 1024

#define STAGES 8
#define DIST   7

#define E2      7.3890560989306495f     // e^2
#define INV_E2  0.1353352832366127f     // e^-2
#define E_P63   2.2937831594696098e27f  // e^63
#define E_M63   4.3596100000630809e-28f // e^-63
#define INV_1ME2 1.1565176427496657f    // 1/(1-e^-2)

// Allocation-free scratch
__device__ float        g_partial[NBLOCKS];
__device__ int          g_pcnt[NBLOCKS];
__device__ unsigned int g_done;

// ---- packed f32x2 helpers (Blackwell; only reachable via PTX) ----
__device__ __forceinline__ unsigned long long pk2(float lo, float hi) {
    unsigned long long r;
    asm("mov.b64 %0, {%1,%2};" : "=l"(r) : "f"(lo), "f"(hi));
    return r;
}
__device__ __forceinline__ void upk2(unsigned long long v, float& lo, float& hi) {
    asm("mov.b64 {%0,%1}, %2;" : "=f"(lo), "=f"(hi) : "l"(v));
}
__device__ __forceinline__ unsigned long long mul2(unsigned long long a, unsigned long long b) {
    unsigned long long r;
    asm("mul.rn.f32x2 %0, %1, %2;" : "=l"(r) : "l"(a), "l"(b));
    return r;
}
__device__ __forceinline__ unsigned long long fma2(unsigned long long a, unsigned long long b,
                                                   unsigned long long c) {
    unsigned long long r;
    asm("fma.rn.f32x2 %0, %1, %2, %3;" : "=l"(r) : "l"(a), "l"(b), "l"(c));
    return r;
}

// entropy = log(sum_d exp(x_d)) - (sum_d w_d*x_d)/spt
// w_d = e^{-|gt-2d|} = min(t_lo*c1, t_hi*c2)  (exact; one side may be +inf)
// spt (closed form, two geometric series):
//   a = gt - 2*floor(gt/2)
//   spt = (e^{-a} - e^{-gt-2} + e^{a-2} - e^{gt-128}) / (1 - e^{-2})
__global__ void __launch_bounds__(TPB, 6)
sce_fused_kernel(const float* __restrict__ sim, const float* __restrict__ gt,
                 float* __restrict__ out) {
    __shared__ float4 buf[STAGES][TPB];    // 32 KB staging

    const int tid = blockIdx.x * TPB + threadIdx.x;
    const int p   = tid * 4;
    const int b   = p / HW;
    const int rem = p - b * HW;

    const float4* simv = (const float4*)(sim + (size_t)b * DD * HW + rem);

    const float4 g = *(const float4*)(gt + p);
    const float gtv[4] = {g.x, g.y, g.z, g.w};

    // Hoisted per-pixel constants
    unsigned long long c1_01, c1_23, c2_01, c2_23;
    {
        float c1[4], c2[4];
        #pragma unroll
        for (int j = 0; j < 4; ++j) {
            c1[j] = __expf(63.0f - gtv[j]);   // 0 when gt = inf
            c2[j] = __expf(gtv[j] - 63.0f);
        }
        c1_01 = pk2(c1[0], c1[1]); c1_23 = pk2(c1[2], c1[3]);
        c2_01 = pk2(c2[0], c2[1]); c2_23 = pk2(c2[2], c2[3]);
    }

    // Prologue: prefetch
    #pragma unroll
    for (int d = 0; d < DIST; ++d) {
        __pipeline_memcpy_async(&buf[d][threadIdx.x],
                                &simv[(size_t)d * (HW / 4)], 16);
        __pipeline_commit();
    }

    float se[4] = {0.f, 0.f, 0.f, 0.f};
    unsigned long long sptx01 = pk2(0.f, 0.f), sptx23 = sptx01;
    unsigned long long t_lo2 = pk2(E_M63, E_M63);
    unsigned long long t_hi2 = pk2(E_P63, E_P63);
    const unsigned long long e2p  = pk2(E2, E2);
    const unsigned long long e2m  = pk2(INV_E2, INV_E2);

    #pragma unroll 4
    for (int d = 0; d < DD; ++d) {
        __pipeline_wait_prior(DIST - 1);
        const float4 x = buf[d & (STAGES - 1)][threadIdx.x];

        const int dn = d + DIST;
        if (dn < DD)
            __pipeline_memcpy_async(&buf[dn & (STAGES - 1)][threadIdx.x],
                                    &simv[(size_t)dn * (HW / 4)], 16);
        __pipeline_commit();

        se[0] += __expf(x.x);
        se[1] += __expf(x.y);
        se[2] += __expf(x.z);
        se[3] += __expf(x.w);

        // w = min(t_lo*c1, t_hi*c2), packed muls + scalar min
        {
            const unsigned long long vlo = mul2(t_lo2, c1_01);
            const unsigned long long vhi = mul2(t_hi2, c2_01);
            float a0, a1, b0, b1;
            upk2(vlo, a0, a1); upk2(vhi, b0, b1);
            const unsigned long long w01 = pk2(fminf(a0, b0), fminf(a1, b1));
            sptx01 = fma2(w01, pk2(x.x, x.y), sptx01);
        }
        {
            const unsigned long long vlo = mul2(t_lo2, c1_23);
            const unsigned long long vhi = mul2(t_hi2, c2_23);
            float a0, a1, b0, b1;
            upk2(vlo, a0, a1); upk2(vhi, b0, b1);
            const unsigned long long w23 = pk2(fminf(a0, b0), fminf(a1, b1));
            sptx23 = fma2(w23, pk2(x.z, x.w), sptx23);
        }

        t_lo2 = mul2(t_lo2, e2p);
        t_hi2 = mul2(t_hi2, e2m);
    }

    float sptx[4];
    upk2(sptx01, sptx[0], sptx[1]);
    upk2(sptx23, sptx[2], sptx[3]);

    float local = 0.f;
    int   cnt   = 0;
    #pragma unroll
    for (int j = 0; j < 4; ++j) {
        const float gv = gtv[j];
        if (isfinite(gv)) {
            // closed-form Laplace normalizer
            const float m  = floorf(gv * 0.5f);
            const float a  = gv - 2.0f * m;
            const float spt = (__expf(-a) - __expf(-gv - 2.0f)
                             + __expf(a - 2.0f) - __expf(gv - 128.0f)) * INV_1ME2;
            local += __logf(se[j]) - __fdividef(sptx[j], spt);
            cnt   += 1;
        }
    }

    // Block reduce (8 warps)
    #pragma unroll
    for (int o = 16; o > 0; o >>= 1) {
        local += __shfl_down_sync(0xffffffffu, local, o);
        cnt   += __shfl_down_sync(0xffffffffu, cnt, o);
    }
    __shared__ float ssum[8];
    __shared__ int   scnt[8];
    __shared__ bool  isLast;
    const int lane = threadIdx.x & 31;
    const int wid  = threadIdx.x >> 5;
    if (lane == 0) { ssum[wid] = local; scnt[wid] = cnt; }
    __syncthreads();
    if (wid == 0) {
        local = (lane < 8) ? ssum[lane] : 0.f;
        cnt   = (lane < 8) ? scnt[lane] : 0;
        #pragma unroll
        for (int o = 4; o > 0; o >>= 1) {
            local += __shfl_down_sync(0xffffffffu, local, o);
            cnt   += __shfl_down_sync(0xffffffffu, cnt, o);
        }
        if (lane == 0) {
            g_partial[blockIdx.x] = local;
            g_pcnt[blockIdx.x]    = cnt;
            __threadfence();
            unsigned int prev = atomicAdd(&g_done, 1u);
            isLast = (prev == (unsigned int)(gridDim.x - 1));
        }
    }
    __syncthreads();

    // Last finished block reduces all partials
    if (isLast) {
        __threadfence();
        const volatile float* vp = g_partial;
        const volatile int*   vc = g_pcnt;
        float s = 0.f;
        int   c = 0;
        #pragma unroll
        for (int k = 0; k < NBLOCKS / TPB; ++k) {
            s += vp[threadIdx.x + k * TPB];
            c += vc[threadIdx.x + k * TPB];
        }
        #pragma unroll
        for (int o = 16; o > 0; o >>= 1) {
            s += __shfl_down_sync(0xffffffffu, s, o);
            c += __shfl_down_sync(0xffffffffu, c, o);
        }
        if (lane == 0) { ssum[wid] = s; scnt[wid] = c; }
        __syncthreads();
        if (wid == 0) {
            s = (lane < 8) ? ssum[lane] : 0.f;
            c = (lane < 8) ? scnt[lane] : 0;
            #pragma unroll
            for (int o = 4; o > 0; o >>= 1) {
                s += __shfl_down_sync(0xffffffffu, s, o);
                c += __shfl_down_sync(0xffffffffu, c, o);
            }
            if (lane == 0) {
                out[0] = s / (float)c;
                g_done = 0;
            }
        }
    }
}

extern "C" void kernel_launch(void* const* d_in, const int* in_sizes, int n_in,
                              void* d_out, int out_size) {
    const float* sim = (const float*)d_in[0];
    const float* gt  = (const float*)d_in[1];
    float* out       = (float*)d_out;

    sce_fused_kernel<<<NBLOCKS, TPB>>>(sim, gt, out);
}

// round 9
// speedup vs baseline: 1.0407x; 1.0407x over previous
#include <cuda_runtime.h>
#include <cuda_pipeline.h>
#include <math.h>

// Problem shape (fixed by reference setup_inputs)
#define BB 8
#define DD 64
#define HW (256 * 512)        // 131072
#define PIXELS (BB * HW)      // 1048576
#define TPB 256
#define NBLOCKS (PIXELS / 4 / TPB)   // 1024

#define STAGES 8
#define DIST   7

#define LOG2E     1.4426950408889634f
#define TWO_LOG2E 2.8853900817779268f
#define INV_1ME2  1.1565176427496657f   // 1/(1-e^-2)

// Allocation-free scratch
__device__ float        g_partial[NBLOCKS];
__device__ int          g_pcnt[NBLOCKS];
__device__ unsigned int g_done;

__device__ __forceinline__ float ex2(float x) {
    float r;
    asm("ex2.approx.f32 %0, %1;" : "=f"(r) : "f"(x));
    return r;
}
__device__ __forceinline__ float lg2(float x) {
    float r;
    asm("lg2.approx.f32 %0, %1;" : "=f"(r) : "f"(x));
    return r;
}

// entropy = log(sum_d exp(x_d)) - (sum_d w_d*x_d)/spt
//   w_d = e^{-|gt-2d|} = ex2(-|dl - gl|),  gl = gt*log2e (hoisted),
//   dl = 2d*log2e (uniform, carried by one FADD per iter)
//   gt = inf -> gl = inf -> w = ex2(-inf) = 0  (self-masking)
// spt closed form (two geometric series), epilogue-only:
//   a = gt - 2*floor(gt/2)
//   spt = (e^{-a} - e^{-gt-2} + e^{a-2} - e^{gt-128}) / (1 - e^{-2})
__global__ void __launch_bounds__(TPB)
sce_fused_kernel(const float* __restrict__ sim, const float* __restrict__ gt,
                 float* __restrict__ out) {
    __shared__ float4 buf[STAGES][TPB];    // 32 KB staging

    const int tid = blockIdx.x * TPB + threadIdx.x;
    const int p   = tid * 4;
    const int b   = p / HW;
    const int rem = p - b * HW;

    const float4* simv = (const float4*)(sim + (size_t)b * DD * HW + rem);

    const float4 g = *(const float4*)(gt + p);
    const float gtv[4] = {g.x, g.y, g.z, g.w};
    float gl[4], se[4], sptx[4];
    #pragma unroll
    for (int j = 0; j < 4; ++j) {
        gl[j]   = gtv[j] * LOG2E;     // inf stays inf
        se[j]   = 0.f;
        sptx[j] = 0.f;
    }

    // Prologue: prefetch d = 0..DIST-1, one commit-group per stage
    #pragma unroll
    for (int d = 0; d < DIST; ++d) {
        __pipeline_memcpy_async(&buf[d][threadIdx.x],
                                &simv[(size_t)d * (HW / 4)], 16);
        __pipeline_commit();
    }

    float dl = 0.0f;   // 2d * log2e, uniform

    #pragma unroll 4
    for (int d = 0; d < DD; ++d) {
        __pipeline_wait_prior(DIST - 1);
        const float4 x = buf[d & (STAGES - 1)][threadIdx.x];

        const int dn = d + DIST;
        if (dn < DD)
            __pipeline_memcpy_async(&buf[dn & (STAGES - 1)][threadIdx.x],
                                    &simv[(size_t)dn * (HW / 4)], 16);
        __pipeline_commit();

        const float xs[4] = {x.x, x.y, x.z, x.w};
        #pragma unroll
        for (int j = 0; j < 4; ++j) {
            const float xx = xs[j];
            se[j]   += ex2(xx * LOG2E);
            const float w = ex2(-fabsf(dl - gl[j]));
            sptx[j] += w * xx;
        }
        dl += TWO_LOG2E;
    }

    float local = 0.f;
    int   cnt   = 0;
    #pragma unroll
    for (int j = 0; j < 4; ++j) {
        const float gv = gtv[j];
        if (isfinite(gv)) {
            const float m   = floorf(gv * 0.5f);
            const float a   = gv - 2.0f * m;
            const float spt = (__expf(-a) - __expf(-gv - 2.0f)
                             + __expf(a - 2.0f) - __expf(gv - 128.0f)) * INV_1ME2;
            // log(se) = lg2(se)/log2e
            local += lg2(se[j]) * (1.0f / LOG2E) - __fdividef(sptx[j], spt);
            cnt   += 1;
        }
    }

    // Block reduce (8 warps)
    #pragma unroll
    for (int o = 16; o > 0; o >>= 1) {
        local += __shfl_down_sync(0xffffffffu, local, o);
        cnt   += __shfl_down_sync(0xffffffffu, cnt, o);
    }
    __shared__ float ssum[8];
    __shared__ int   scnt[8];
    __shared__ bool  isLast;
    const int lane = threadIdx.x & 31;
    const int wid  = threadIdx.x >> 5;
    if (lane == 0) { ssum[wid] = local; scnt[wid] = cnt; }
    __syncthreads();
    if (wid == 0) {
        local = (lane < 8) ? ssum[lane] : 0.f;
        cnt   = (lane < 8) ? scnt[lane] : 0;
        #pragma unroll
        for (int o = 4; o > 0; o >>= 1) {
            local += __shfl_down_sync(0xffffffffu, local, o);
            cnt   += __shfl_down_sync(0xffffffffu, cnt, o);
        }
        if (lane == 0) {
            g_partial[blockIdx.x] = local;
            g_pcnt[blockIdx.x]    = cnt;
            __threadfence();
            unsigned int prev = atomicAdd(&g_done, 1u);
            isLast = (prev == (unsigned int)(gridDim.x - 1));
        }
    }
    __syncthreads();

    // Last finished block reduces all partials
    if (isLast) {
        __threadfence();
        const volatile float* vp = g_partial;
        const volatile int*   vc = g_pcnt;
        float s = 0.f;
        int   c = 0;
        #pragma unroll
        for (int k = 0; k < NBLOCKS / TPB; ++k) {
            s += vp[threadIdx.x + k * TPB];
            c += vc[threadIdx.x + k * TPB];
        }
        #pragma unroll
        for (int o = 16; o > 0; o >>= 1) {
            s += __shfl_down_sync(0xffffffffu, s, o);
            c += __shfl_down_sync(0xffffffffu, c, o);
        }
        if (lane == 0) { ssum[wid] = s; scnt[wid] = c; }
        __syncthreads();
        if (wid == 0) {
            s = (lane < 8) ? ssum[lane] : 0.f;
            c = (lane < 8) ? scnt[lane] : 0;
            #pragma unroll
            for (int o = 4; o > 0; o >>= 1) {
                s += __shfl_down_sync(0xffffffffu, s, o);
                c += __shfl_down_sync(0xffffffffu, c, o);
            }
            if (lane == 0) {
                out[0] = s / (float)c;
                g_done = 0;
            }
        }
    }
}

extern "C" void kernel_launch(void* const* d_in, const int* in_sizes, int n_in,
                              void* d_out, int out_size) {
    const float* sim = (const float*)d_in[0];
    const float* gt  = (const float*)d_in[1];
    float* out       = (float*)d_out;

    sce_fused_kernel<<<NBLOCKS, TPB>>>(sim, gt, out);
}

// round 10
// speedup vs baseline: 1.0804x; 1.0381x over previous
#include <cuda_runtime.h>
#include <cuda_pipeline.h>
#include <math.h>

// Problem shape (fixed by reference setup_inputs)
#define BB 8
#define DD 64
#define HW (256 * 512)        // 131072
#define PIXELS (BB * HW)      // 1048576
#define TPB 128
#define PPT 8                 // pixels per thread
#define NBLOCKS (PIXELS / PPT / TPB)   // 1024

#define STAGES 8
#define DIST   7

#define LOG2E     1.4426950408889634f
#define INV_LOG2E 0.6931471805599453f
#define TWO_LOG2E 2.8853900817779268f
#define INV_1ME2  1.1565176427496657f   // 1/(1-e^-2)

// Allocation-free scratch
__device__ float        g_partial[NBLOCKS];
__device__ int          g_pcnt[NBLOCKS];
__device__ unsigned int g_done;

__device__ __forceinline__ float ex2(float x) {
    float r;
    asm("ex2.approx.f32 %0, %1;" : "=f"(r) : "f"(x));
    return r;
}
__device__ __forceinline__ float lg2(float x) {
    float r;
    asm("lg2.approx.f32 %0, %1;" : "=f"(r) : "f"(x));
    return r;
}

// All math in base 2 (one lg2-scale fold at epilogue):
//   xl = x*log2e;  se += ex2(xl);  w = ex2(-|dl - gl|);  sptx' += w*xl
//   entropy = (lg2(se) - sptx'/spt') / log2e   with spt' = spt*log2e... no:
//   sptx'/ (log2e) / spt = Sum w x / spt; entropy = lg2(se)/log2e - sptx'/(log2e*spt)
//           = (lg2(se) - sptx'/spt) / log2e
// gt = inf -> gl = inf -> w = 0 (self-masking). spt via closed form (epilogue).
__global__ void __launch_bounds__(TPB)
sce_fused_kernel(const float* __restrict__ sim, const float* __restrict__ gt,
                 float* __restrict__ out) {
    __shared__ float4 buf[STAGES][TPB * 2];    // 32 KB staging (2 float4/thread/stage)

    const int tid = blockIdx.x * TPB + threadIdx.x;
    const int p   = tid * PPT;
    const int b   = p / HW;
    const int rem = p - b * HW;

    const float4* simv = (const float4*)(sim + (size_t)b * DD * HW + rem);

    float gtv[PPT], gl[PPT], se[PPT], sptx[PPT];
    {
        const float4 g0 = *(const float4*)(gt + p);
        const float4 g1 = *(const float4*)(gt + p + 4);
        gtv[0]=g0.x; gtv[1]=g0.y; gtv[2]=g0.z; gtv[3]=g0.w;
        gtv[4]=g1.x; gtv[5]=g1.y; gtv[6]=g1.z; gtv[7]=g1.w;
    }
    #pragma unroll
    for (int j = 0; j < PPT; ++j) {
        gl[j]   = gtv[j] * LOG2E;     // inf stays inf
        se[j]   = 0.f;
        sptx[j] = 0.f;
    }

    // Prologue: prefetch d = 0..DIST-1 (2 x 16B per stage, one group per stage)
    #pragma unroll
    for (int d = 0; d < DIST; ++d) {
        __pipeline_memcpy_async(&buf[d][threadIdx.x * 2 + 0],
                                &simv[(size_t)d * (HW / 4) + 0], 16);
        __pipeline_memcpy_async(&buf[d][threadIdx.x * 2 + 1],
                                &simv[(size_t)d * (HW / 4) + 1], 16);
        __pipeline_commit();
    }

    float dl = 0.0f;   // 2d * log2e, uniform

    #pragma unroll 4
    for (int d = 0; d < DD; ++d) {
        __pipeline_wait_prior(DIST - 1);
        const int st = d & (STAGES - 1);
        const float4 x0 = buf[st][threadIdx.x * 2 + 0];
        const float4 x1 = buf[st][threadIdx.x * 2 + 1];

        const int dn = d + DIST;
        if (dn < DD) {
            const int sn = dn & (STAGES - 1);
            __pipeline_memcpy_async(&buf[sn][threadIdx.x * 2 + 0],
                                    &simv[(size_t)dn * (HW / 4) + 0], 16);
            __pipeline_memcpy_async(&buf[sn][threadIdx.x * 2 + 1],
                                    &simv[(size_t)dn * (HW / 4) + 1], 16);
        }
        __pipeline_commit();

        const float xs[PPT] = {x0.x, x0.y, x0.z, x0.w, x1.x, x1.y, x1.z, x1.w};
        #pragma unroll
        for (int j = 0; j < PPT; ++j) {
            const float xl = xs[j] * LOG2E;
            se[j]   += ex2(xl);
            const float w = ex2(-fabsf(dl - gl[j]));
            sptx[j] += w * xl;
        }
        dl += TWO_LOG2E;
    }

    float local = 0.f;
    int   cnt   = 0;
    #pragma unroll
    for (int j = 0; j < PPT; ++j) {
        const float gv = gtv[j];
        if (isfinite(gv)) {
            const float m   = floorf(gv * 0.5f);
            const float a   = gv - 2.0f * m;
            const float spt = (__expf(-a) - __expf(-gv - 2.0f)
                             + __expf(a - 2.0f) - __expf(gv - 128.0f)) * INV_1ME2;
            local += (lg2(se[j]) - __fdividef(sptx[j], spt)) * INV_LOG2E;
            cnt   += 1;
        }
    }

    // Block reduce (4 warps)
    #pragma unroll
    for (int o = 16; o > 0; o >>= 1) {
        local += __shfl_down_sync(0xffffffffu, local, o);
        cnt   += __shfl_down_sync(0xffffffffu, cnt, o);
    }
    __shared__ float ssum[4];
    __shared__ int   scnt[4];
    __shared__ bool  isLast;
    const int lane = threadIdx.x & 31;
    const int wid  = threadIdx.x >> 5;
    if (lane == 0) { ssum[wid] = local; scnt[wid] = cnt; }
    __syncthreads();
    if (wid == 0) {
        local = (lane < 4) ? ssum[lane] : 0.f;
        cnt   = (lane < 4) ? scnt[lane] : 0;
        #pragma unroll
        for (int o = 2; o > 0; o >>= 1) {
            local += __shfl_down_sync(0xffffffffu, local, o);
            cnt   += __shfl_down_sync(0xffffffffu, cnt, o);
        }
        if (lane == 0) {
            g_partial[blockIdx.x] = local;
            g_pcnt[blockIdx.x]    = cnt;
            __threadfence();
            unsigned int prev = atomicAdd(&g_done, 1u);
            isLast = (prev == (unsigned int)(gridDim.x - 1));
        }
    }
    __syncthreads();

    // Last finished block reduces all partials
    if (isLast) {
        __threadfence();
        const volatile float* vp = g_partial;
        const volatile int*   vc = g_pcnt;
        float s = 0.f;
        int   c = 0;
        #pragma unroll
        for (int k = 0; k < NBLOCKS / TPB; ++k) {
            s += vp[threadIdx.x + k * TPB];
            c += vc[threadIdx.x + k * TPB];
        }
        #pragma unroll
        for (int o = 16; o > 0; o >>= 1) {
            s += __shfl_down_sync(0xffffffffu, s, o);
            c += __shfl_down_sync(0xffffffffu, c, o);
        }
        if (lane == 0) { ssum[wid] = s; scnt[wid] = c; }
        __syncthreads();
        if (wid == 0) {
            s = (lane < 4) ? ssum[lane] : 0.f;
            c = (lane < 4) ? scnt[lane] : 0;
            #pragma unroll
            for (int o = 2; o > 0; o >>= 1) {
                s += __shfl_down_sync(0xffffffffu, s, o);
                c += __shfl_down_sync(0xffffffffu, c, o);
            }
            if (lane == 0) {
                out[0] = s / (float)c;
                g_done = 0;
            }
        }
    }
}

extern "C" void kernel_launch(void* const* d_in, const int* in_sizes, int n_in,
                              void* d_out, int out_size) {
    const float* sim = (const float*)d_in[0];
    const float* gt  = (const float*)d_in[1];
    float* out       = (float*)d_out;

    sce_fused_kernel<<<NBLOCKS, TPB>>>(sim, gt, out);
}